// round 15
// baseline (speedup 1.0000x reference)
#include <cuda_runtime.h>
#include <cstdint>

#define MAXR 100.0f
#define PLANE 1280   // 64 channels * 20 floats per row-plane

__device__ __forceinline__ float tanh_fast(float x) {
    float r;
    asm("tanh.approx.f32 %0, %1;" : "=f"(r) : "f"(x));
    return r;
}

// Accurate fast tanh: 1 - 2/(1+e^{2s}). ~1e-7 abs err, saturates correctly.
__device__ __forceinline__ float tanh_exp(float s) {
    float e2 = __expf(2.0f * s);
    return 1.0f - __fdividef(2.0f, 1.0f + e2);
}

// Max of NONNEGATIVE floats via integer redux (bit order == value order).
__device__ __forceinline__ float warp_max_nn(float v) {
    unsigned r;
    asm("redux.sync.max.u32 %0, %1, 0xffffffff;"
        : "=r"(r) : "r"(__float_as_uint(v)));
    return __uint_as_float(r);
}

// Parity-folded warp add: even lanes end with full 32-lane sum of va,
// odd lanes with that of vb.
__device__ __forceinline__ float fold_add(float va, float vb, int bit) {
    float send = bit ? va : vb;
    float keep = bit ? vb : va;
    float r = keep + __shfl_xor_sync(0xffffffffu, send, 1);
    #pragma unroll
    for (int o = 2; o < 32; o <<= 1)
        r += __shfl_xor_sync(0xffffffffu, r, o);
    return r;
}

// ---------------------------------------------------------------------------
// Persistent rolling-strip kernel.
// Grid 128 x 256 threads. Block = 16-wide x 8-row strip:
//   mega = bi>>3 -> (batch, colstrip), h0 = (bi&7)*8, w0 = colstrip*16.
// Smem ring of 5 row-planes (plane = 64ch x [16 centers | right halo @16 |
// left halo @17 | 2 pad], stride 20 -> 16B-aligned cp.async, LDS.64-legal
// conv windows). Per step s (row h = h0+s):
//   issue cp.async prefetch of plane h+2 into slot (s+3)%5, commit,
//   wait_group 1 (planes through h+1 complete), __syncthreads, compute.
// Ring-of-5 guarantees the written slot never collides with any slot read
// by threads still in the previous step, so ONE barrier per step suffices.
// Conv weights are held in registers (loaded once). Epilogue per step =
// parity-folded reductions + C0 screen (uniform softmax -> mean) + rare
// exact tanh path.
// ---------------------------------------------------------------------------
__global__ __launch_bounds__(256, 2) void dsf_persist_kernel(
    const float* __restrict__ x,
    const float* __restrict__ wgt,
    const float* __restrict__ bias,
    float* __restrict__ out) {

    __shared__ float ring[5 * PLANE];   // 25.6 KB

    int tid  = threadIdx.x;
    int bi   = blockIdx.x;
    int mega = bi >> 3;                 // 0..15
    int h0   = (bi & 7) * 8;
    int b    = mega >> 2;
    int w0   = (mega & 3) * 16;
    const float* xb = x + b * 262144;

    int lane   = tid & 31;
    int wid    = tid >> 5;              // warp 0..7 -> pixels 2w, 2w+1
    int parity = lane & 1;
    int wc     = wid * 2;               // pixel A col in [0,16), even

    // ---- Per-lane conv weights in registers (channels lane, lane+32) ------
    float Wa0[9], Wa1[9], Wb0[9], Wb1[9];   // [ch g][out]
    {
        const float* p = wgt + lane * 9;
        #pragma unroll
        for (int t = 0; t < 9; t++) { Wa0[t] = __ldg(p + t); Wa1[t] = __ldg(p + 576 + t); }
        const float* q = wgt + (lane + 32) * 9;
        #pragma unroll
        for (int t = 0; t < 9; t++) { Wb0[t] = __ldg(q + t); Wb1[t] = __ldg(q + 576 + t); }
    }
    float b0 = __ldg(&bias[0]);
    float b1 = __ldg(&bias[1]);

    uint32_t smem0;
    asm("{ .reg .u64 t; cvta.to.shared.u64 t, %1; cvt.u32.u64 %0, t; }"
        : "=r"(smem0) : "l"(ring));

    // Per-thread plane-load roles (constant across steps).
    int lc = tid >> 2, lf = tid & 3;            // center: channel, float4 idx
    int hc = tid >> 1, hside = tid & 1;          // halo (tid<128): ch, side
    int hcol = hside ? (w0 + 16) : (w0 - 1);     // side1=right(j16), 0=left(j17)
    bool hcol_ok = (unsigned)hcol < 64u;

    auto load_plane = [&](int hh, int slot) {
        bool valid = (unsigned)hh < 64u;
        uint32_t dst = smem0 + (uint32_t)(slot * PLANE + lc * 20 + lf * 4) * 4u;
        const float* src = xb + lc * 4096 + hh * 64 + w0 + lf * 4;
        if (valid)
            asm volatile("cp.async.cg.shared.global [%0], [%1], 16;"
                         :: "r"(dst), "l"(src));
        else
            asm volatile("st.shared.v4.b32 [%0], {%1,%1,%1,%1};"
                         :: "r"(dst), "r"(0));
        if (tid < 128) {
            uint32_t d2 = smem0 +
                (uint32_t)(slot * PLANE + hc * 20 + (hside ? 16 : 17)) * 4u;
            const float* s2 = xb + hc * 4096 + hh * 64 + hcol;
            if (valid && hcol_ok)
                asm volatile("cp.async.ca.shared.global [%0], [%1], 4;"
                             :: "r"(d2), "l"(s2));
            else
                asm volatile("st.shared.b32 [%0], %1;" :: "r"(d2), "r"(0));
        }
    };

    // ---- Prime: planes h0-1, h0, h0+1 -> slots 0,1,2 (3 groups) -----------
    load_plane(h0 - 1, 0); asm volatile("cp.async.commit_group;");
    load_plane(h0,     1); asm volatile("cp.async.commit_group;");
    load_plane(h0 + 1, 2); asm volatile("cp.async.commit_group;");

    int sl0 = 0, sl1 = 1, sl2 = 2, slw = 3;     // rotating ring slots

    for (int s = 0; s < 8; s++) {
        // Prefetch plane h+2 (skip past strip end; still commit for counting).
        if (s < 7) load_plane(h0 + s + 2, slw);
        asm volatile("cp.async.commit_group;");
        asm volatile("cp.async.wait_group 1;");  // planes through h+1 done
        __syncthreads();

        int r0 = sl0 * PLANE, r1 = sl1 * PLANE, r2 = sl2 * PLANE;

        // ---- Conv for pixels (wc, wc+1); weights from registers ----------
        float cA0 = 0.f, cA1 = 0.f, cB0 = 0.f, cB1 = 0.f;
        float xa0, xa1, xbv0, xbv1;
        #pragma unroll
        for (int g = 0; g < 2; g++) {
            int cb = (lane + g * 32) * 20;
            const float* W0 = g ? Wb0 : Wa0;
            const float* W1 = g ? Wb1 : Wa1;
            #pragma unroll
            for (int rr = 0; rr < 3; rr++) {
                int ro = (rr == 0) ? r0 : ((rr == 1) ? r1 : r2);
                float2 mid = *reinterpret_cast<const float2*>(&ring[ro + cb + wc]);
                float2 hi  = *reinterpret_cast<const float2*>(&ring[ro + cb + wc + 2]);
                float loy;
                if (wid >= 1) {
                    float2 lo = *reinterpret_cast<const float2*>(&ring[ro + cb + wc - 2]);
                    loy = lo.y;
                } else {
                    loy = ring[ro + cb + 17];    // left halo
                }
                float w00 = W0[rr * 3], w01 = W0[rr * 3 + 1], w02 = W0[rr * 3 + 2];
                float w10 = W1[rr * 3], w11 = W1[rr * 3 + 1], w12 = W1[rr * 3 + 2];
                cA0 = fmaf(loy,   w00, cA0);  cA1 = fmaf(loy,   w10, cA1);
                cA0 = fmaf(mid.x, w01, cA0);  cA1 = fmaf(mid.x, w11, cA1);
                cA0 = fmaf(mid.y, w02, cA0);  cA1 = fmaf(mid.y, w12, cA1);
                cB0 = fmaf(mid.x, w00, cB0);  cB1 = fmaf(mid.x, w10, cB1);
                cB0 = fmaf(mid.y, w01, cB0);  cB1 = fmaf(mid.y, w11, cB1);
                cB0 = fmaf(hi.x,  w02, cB0);  cB1 = fmaf(hi.x,  w12, cB1);
                if (rr == 1) {                   // center row: channel values
                    if (g == 0) { xa0 = mid.x; xbv0 = mid.y; }
                    else        { xa1 = mid.x; xbv1 = mid.y; }
                }
            }
        }

        // ---- Reductions (parity fold + redux max) ------------------------
        float ss = fold_add(xa0 + xa1, xbv0 + xbv1, parity);
        float sa = fold_add(fabsf(xa0) + fabsf(xa1),
                            fabsf(xbv0) + fabsf(xbv1), parity);
        float c0 = fold_add(cA0, cB0, parity);
        float c1 = fold_add(cA1, cB1, parity);
        float smA = warp_max_nn(fmaxf(fabsf(xa0), fabsf(xa1)));
        float smB = warp_max_nn(fmaxf(fabsf(xbv0), fabsf(xbv1)));
        float sm  = parity ? smB : smA;

        float alpha = MAXR * tanh_exp(c0 + b0);
        float beta  = MAXR * tanh_exp(c1 + b1);

        int op0 = b * 4096 + (h0 + s) * 64 + w0 + wc;

        // ---- Screen C0: all logits clip -> uniform softmax -> mean -------
        bool ok = fabsf(alpha) * (fabsf(beta) * (sa * (1.0f / 64.0f)) - sm)
                  >= 101.0f;
        if (lane < 2 && ok) out[op0 + lane] = ss * (1.0f / 64.0f);

        if (!__all_sync(0xffffffffu, ok)) {
            // ---- Exact path(s) (rare) ------------------------------------
            #pragma unroll
            for (int p = 0; p < 2; p++) {
                if (__shfl_sync(0xffffffffu, (int)ok, p)) continue;
                float al = __shfl_sync(0xffffffffu, alpha, p);
                float be = __shfl_sync(0xffffffffu, beta, p);
                float xj0 = p ? xbv0 : xa0;
                float xj1 = p ? xbv1 : xa1;

                float ab  = al * be;
                float nc0 = -al * xj0;
                float nc1 = -al * xj1;
                const float* xc = &ring[r1 + wc + p];

                float acc0 = 0.0f, acc1 = 0.0f;
                #pragma unroll 8
                for (int i = 0; i < 64; i++) {
                    float xi = xc[i * 20];       // LDS broadcast over channels
                    float z0 = fmaf(ab, xi, nc0);
                    float z1 = fmaf(ab, xi, nc1);
                    acc0 = fmaf(z0, tanh_fast(z0), acc0);
                    acc1 = fmaf(z1, tanh_fast(z1), acc1);
                }
                float l0 = fminf(fmaxf(acc0 * (-1.0f / 64.0f), -MAXR), MAXR);
                float l1 = fminf(fmaxf(acc1 * (-1.0f / 64.0f), -MAXR), MAXR);
                float m = fmaxf(l0, l1);
                #pragma unroll
                for (int o = 16; o > 0; o >>= 1)
                    m = fmaxf(m, __shfl_xor_sync(0xffffffffu, m, o));
                float e0 = __expf(l0 - m);
                float e1 = __expf(l1 - m);
                float num = fmaf(xj0, e0, xj1 * e1);
                float den = e0 + e1;
                #pragma unroll
                for (int o = 16; o > 0; o >>= 1) {
                    num += __shfl_xor_sync(0xffffffffu, num, o);
                    den += __shfl_xor_sync(0xffffffffu, den, o);
                }
                if (lane == 0) out[op0 + p] = num / den;
            }
        }

        // Rotate ring slots (no end barrier needed: ring-of-5 keeps the next
        // step's write slot disjoint from every slot still being read).
        sl0 = sl1; sl1 = sl2; sl2 = slw;
        slw = (slw + 1 == 5) ? 0 : slw + 1;
    }
}

extern "C" void kernel_launch(void* const* d_in, const int* in_sizes, int n_in,
                              void* d_out, int out_size) {
    const float* x    = (const float*)d_in[0];
    const float* w    = (const float*)d_in[1];
    const float* bias = (const float*)d_in[2];
    float* out        = (float*)d_out;

    dsf_persist_kernel<<<128, 256>>>(x, w, bias, out);
}